// round 17
// baseline (speedup 1.0000x reference)
#include <cuda_runtime.h>
#include <cuda_fp16.h>
#include <math.h>
#include <stdint.h>

// Problem constants
#define Bn 2
#define Tn 32
#define Nn 64
#define FINn 64
#define FOUTn 64
#define EDIMn 16
#define BT (Bn*Tn)            // 64
#define ROWS (BT*Nn)          // 4096
#define NBLK 256              // all CTAs co-resident: 2/SM * 148 = 296 >= 256

// -------- device scratch --------
__device__ __half g_xnh[ROWS*FINn];        // xn fp16 [bt*64+j][f]
__device__ __half g_h[Bn*EDIMn*Nn*Nn];     // h fp16 [b][e][i][j]
__device__ __half g_w2[EDIMn*FINn*FOUTn];  // ew2 fp16 [e][f][o]
__device__ __half g_nw[FINn*FOUTn];        // nw fp16 [f][o]
__device__ float g_part[4][BT*Nn*FOUTn];   // per-eg partials (node-lin quartered)
__device__ float g_T2[BT*FOUTn];           // eb2 contribution
__device__ unsigned g_bcnt;                // global barrier counter (ends at 0)
__device__ unsigned g_btcnt[BT];           // per-bt completion counters (end at 0)

__device__ __forceinline__ float gelu_exact(float v) {
    return 0.5f * v * (1.0f + erff(v * 0.70710678118654752f));
}
__device__ __forceinline__ uint32_t pack_f16(__half a, __half b) {
    return ((uint32_t)__half_as_ushort(b) << 16) | (uint32_t)__half_as_ushort(a);
}
__device__ __forceinline__ uint32_t smem_u32(const void* p) {
    uint32_t a;
    asm("{ .reg .u64 t; cvta.to.shared.u64 t, %1; cvt.u32.u64 %0, t; }" : "=r"(a) : "l"(p));
    return a;
}

#define LDM_X4(r0,r1,r2,r3,addr) \
    asm volatile("ldmatrix.sync.aligned.m8n8.x4.shared.b16 {%0,%1,%2,%3}, [%4];" \
        : "=r"(r0),"=r"(r1),"=r"(r2),"=r"(r3) : "r"(addr))
#define LDM_X4T(r0,r1,r2,r3,addr) \
    asm volatile("ldmatrix.sync.aligned.m8n8.x4.trans.shared.b16 {%0,%1,%2,%3}, [%4];" \
        : "=r"(r0),"=r"(r1),"=r"(r2),"=r"(r3) : "r"(addr))

__device__ __forceinline__ void mma_f16(float* c, const uint32_t* a, uint32_t b0, uint32_t b1) {
    asm volatile("mma.sync.aligned.m16n8k16.row.col.f32.f16.f16.f32 "
        "{%0,%1,%2,%3}, {%4,%5,%6,%7}, {%8,%9}, {%0,%1,%2,%3};"
        : "+f"(c[0]), "+f"(c[1]), "+f"(c[2]), "+f"(c[3])
        : "r"(a[0]), "r"(a[1]), "r"(a[2]), "r"(a[3]), "r"(b0), "r"(b1));
}

#define CP_ASYNC16(saddr, gptr) \
    asm volatile("cp.async.cg.shared.global [%0], [%1], 16;" \
        :: "r"(saddr), "l"(__cvta_generic_to_global(gptr)) : "memory")
#define CP_COMMIT() asm volatile("cp.async.commit_group;" ::: "memory")
#define CP_WAIT0()  asm volatile("cp.async.wait_group 0;" ::: "memory")

// Single global barrier: atomicInc wrapping at NBLK-1 -> last arrival sets 0.
__device__ __forceinline__ void gbar() {
    __syncthreads();
    if (threadIdx.x == 0) {
        __threadfence();
        atomicInc(&g_bcnt, NBLK - 1u);
        volatile unsigned* p = &g_bcnt;
        while (*p != 0u) {}
        __threadfence();
    }
    __syncthreads();
}

#define LDA 72
#define TILE (64*LDA)           // 4608 halves = 9216 B
#define FUS_SMEM (12*TILE*2)    // 110592 B -> 2 CTAs/SM (221184 <= 228KB)

__global__ void __launch_bounds__(256, 2)
k_all(const float* __restrict__ x,   const float* __restrict__ adj,
      const float* __restrict__ ew1, const float* __restrict__ eb1,
      const float* __restrict__ ew2, const float* __restrict__ eb2,
      const float* __restrict__ nw,  const float* __restrict__ nb,
      const float* __restrict__ gw,  const float* __restrict__ gb,
      const float* __restrict__ gms, float* __restrict__ out) {
    extern __shared__ __align__(16) __half ds[];
    __shared__ unsigned s_old;
    int tid = threadIdx.x, blk = blockIdx.x;

    // =================== PHASE A: prologue ===================
    if (blk < BT) {
        // ---- norm + T2 for bt = blk ----
        int bt = blk;
        int f = tid & 63;
        int g = tid >> 6;
        float* sA   = (float*)ds;               // [4][64]
        float* sB   = sA + 256;
        float* sMul = sB + 256;
        float* sSub = sMul + 64;
        float* sAdd = sSub + 64;
        float* sSf  = sAdd + 64;

        const float* xp = x + bt * (Nn * FINn) + f;
        float s = 0.f, ss = 0.f;
#pragma unroll
        for (int n = g * 16; n < g * 16 + 16; n++) {
            float v = xp[n * FINn];
            s += v; ss += v * v;
        }
        sA[g * 64 + f] = s; sB[g * 64 + f] = ss;
        __syncthreads();

        if (g == 0) {
            float st  = sA[f] + sA[64 + f] + sA[128 + f] + sA[192 + f];
            float sst = sB[f] + sB[64 + f] + sB[128 + f] + sB[192 + f];
            float mean = st * (1.0f / Nn);
            float var  = sst * (1.0f / Nn) - mean * mean;
            float rstd = rsqrtf(var + 1e-5f);
            float w = gw[f], bbv = gb[f];
            float sub = mean * gms[0];
            sMul[f] = rstd * w;
            sSub[f] = sub;
            sAdd[f] = bbv;
            sSf[f]  = (float)Nn * ((mean - sub) * rstd * w + bbv);
        }
        __syncthreads();

        float mul = sMul[f], sub = sSub[f], add = sAdd[f];
#pragma unroll
        for (int n = g * 16; n < g * 16 + 16; n++) {
            float v = (xp[n * FINn] - sub) * mul + add;
            g_xnh[bt * 4096 + n * 64 + f] = __float2half_rn(v);
        }

        int o = f;
        float acc = 0.f;
#pragma unroll
        for (int ff = g * 16; ff < g * 16 + 16; ff++)
            acc += sSf[ff] * eb2[ff * FOUTn + o];
        __syncthreads();
        sA[g * 64 + o] = acc;
        __syncthreads();
        if (g == 0)
            g_T2[bt * FOUTn + o] = sA[o] + sA[64 + o] + sA[128 + o] + sA[192 + o];
        __syncthreads();
    } else if (blk < BT + 16) {
        // nw convert: 4096 elems over blocks 64..79
        int idx = (blk - BT) * 256 + tid;
        g_nw[idx] = __float2half_rn(nw[idx]);
    }

    // edge (all blocks): 131072 elems, 2/thread, fp16
    {
        int idx2 = blk * 512 + tid * 2;
        int row = idx2 >> 6;                    // (b,e,i)
        int j = idx2 & 63;
        int b = row >> 10, e = (row >> 6) & 15, i = row & 63;
        float2 a2 = *(const float2*)(adj + b * 4096 + i * 64 + j);
        float w1 = ew1[e], b1 = eb1[e];
        __half h0 = __float2half_rn(gelu_exact(a2.x * w1 + b1));
        __half h1 = __float2half_rn(gelu_exact(a2.y * w1 + b1));
        *(uint32_t*)(g_h + idx2) = pack_f16(h0, h1);
    }
    // ew2 convert (all blocks): 65536 elems, 1/thread
    {
        int idx = blk * 256 + tid;
        g_w2[idx] = __float2half_rn(ew2[idx]);
    }

    gbar();

    // =================== PHASE B: single-burst fused GEMM + finisher ===================
    {
        // Tile map: T0 = X (persistent), T1 = P0, T2 = P1,
        //           T3..T6 = W0..W3 (T3,T4 recycled as P2,P3),
        //           T7..T10 = H0..H3, T11 = NW quarter patch (all blocks)
        __half *Xs = ds;
        __half *Pt01[2] = { ds + TILE, ds + 2*TILE };
        __half *Wt[4] = { ds + 3*TILE, ds + 4*TILE, ds + 5*TILE, ds + 6*TILE };
        __half *Pt23[2] = { ds + 3*TILE, ds + 4*TILE };     // recycle W0, W1
        __half *Ht[4] = { ds + 7*TILE, ds + 8*TILE, ds + 9*TILE, ds + 10*TILE };
        __half *NWt = ds + 11*TILE;

        int warp = tid >> 5, lane = tid & 31;
        int wr = warp >> 1, wc = warp & 1;
        int bt = blk >> 2, eg = blk & 3;
        int b = bt >> 5;

        // ---- single burst: X + W0..3 + H0..3 + nw quarter patch ----
        {
            const __half* xhp = g_xnh + bt * 4096;
            uint32_t sX = smem_u32(Xs);
#pragma unroll
            for (int l = 0; l < 2; l++) {
                int idx = tid + l * 256;
                int r = idx >> 3, q = idx & 7;
                uint32_t off = (uint32_t)(r * LDA + q * 8) * 2;
                CP_ASYNC16(sX + off, xhp + r * 64 + q * 8);
            }
#pragma unroll
            for (int e2 = 0; e2 < 4; e2++) {
                int e = eg * 4 + e2;
                uint32_t sW = smem_u32(Wt[e2]), sH = smem_u32(Ht[e2]);
                const __half* wp = g_w2 + e * 4096;
                const __half* hp = g_h + (b * 16 + e) * 4096;
#pragma unroll
                for (int l = 0; l < 2; l++) {
                    int idx = tid + l * 256;
                    int r = idx >> 3, q = idx & 7;
                    uint32_t off = (uint32_t)(r * LDA + q * 8) * 2;
                    CP_ASYNC16(sW + off, wp + r * 64 + q * 8);
                    CP_ASYNC16(sH + off, hp + r * 64 + q * 8);
                }
            }
            // nw quarter: 64 rows x 16 cols (this block's output columns eg*16..+16)
            if (tid < 128) {
                int r = tid >> 1, hf = tid & 1;
                CP_ASYNC16(smem_u32(NWt) + (uint32_t)(r * LDA + hf * 8) * 2,
                           g_nw + r * 64 + eg * 16 + hf * 8);
            }
            CP_COMMIT();
        }
        CP_WAIT0();
        __syncthreads();                        // sync 1: all tiles resident

        uint32_t xB = smem_u32(Xs);
        int g = lane >> 3, lr = lane & 7;
        int arow = wr * 16 + (g & 1) * 8 + lr;
        int acol0 = (g >> 1) * 8;

        // persistent xn A-fragments (X tile never overwritten -> no extra sync)
        uint32_t xh[16];
#pragma unroll
        for (int ks = 0; ks < 4; ks++) {
            uint32_t off = (uint32_t)(arow * LDA + ks * 16 + acol0) * 2;
            LDM_X4(xh[4*ks], xh[4*ks+1], xh[4*ks+2], xh[4*ks+3], xB + off);
        }

        float agg[4][4];
#pragma unroll
        for (int i = 0; i < 4; i++) { agg[i][0]=0.f; agg[i][1]=0.f; agg[i][2]=0.f; agg[i][3]=0.f; }

        int cr = lane >> 2, cc2 = (lane & 3) * 2;

#define DO_MMA1(WSRC, PDST)                                                    \
        {                                                                      \
            uint32_t wB = smem_u32(WSRC);                                      \
            __half* Pt = (PDST);                                               \
            _Pragma("unroll")                                                  \
            for (int nt = 0; nt < 4; nt++) {                                   \
                float p[4] = {0.f,0.f,0.f,0.f};                                \
                uint32_t bw[8];                                                \
                uint32_t off1 = (uint32_t)((g * 8 + lr) * LDA + wc * 32 + nt * 8) * 2;        \
                uint32_t off2 = (uint32_t)((32 + g * 8 + lr) * LDA + wc * 32 + nt * 8) * 2;   \
                LDM_X4T(bw[0], bw[1], bw[2], bw[3], wB + off1);                \
                LDM_X4T(bw[4], bw[5], bw[6], bw[7], wB + off2);                \
                _Pragma("unroll")                                              \
                for (int ks = 0; ks < 4; ks++)                                 \
                    mma_f16(p, xh + 4*ks, bw[2*ks], bw[2*ks+1]);               \
                _Pragma("unroll")                                              \
                for (int half = 0; half < 2; half++) {                         \
                    int row = wr * 16 + cr + half * 8;                         \
                    int col = wc * 32 + nt * 8 + cc2;                          \
                    *(uint32_t*)(Pt + row * LDA + col) =                       \
                        pack_f16(__float2half_rn(p[half*2]), __float2half_rn(p[half*2+1])); \
                }                                                              \
            }                                                                  \
        }

#define DO_MMA2(HSRC, PSRC)                                                    \
        {                                                                      \
            uint32_t hB = smem_u32(HSRC);                                      \
            uint32_t pBq = smem_u32(PSRC);                                     \
            uint32_t ahh[16];                                                  \
            _Pragma("unroll")                                                  \
            for (int ks = 0; ks < 4; ks++) {                                   \
                uint32_t off = (uint32_t)(arow * LDA + ks * 16 + acol0) * 2;   \
                LDM_X4(ahh[4*ks], ahh[4*ks+1], ahh[4*ks+2], ahh[4*ks+3], hB + off); \
            }                                                                  \
            _Pragma("unroll")                                                  \
            for (int kh = 0; kh < 2; kh++) {                                   \
                _Pragma("unroll")                                              \
                for (int nt = 0; nt < 4; nt++) {                               \
                    uint32_t bp[4];                                            \
                    uint32_t off = (uint32_t)((kh * 32 + g * 8 + lr) * LDA + wc * 32 + nt * 8) * 2; \
                    LDM_X4T(bp[0], bp[1], bp[2], bp[3], pBq + off);            \
                    _Pragma("unroll")                                          \
                    for (int k2 = 0; k2 < 2; k2++) {                           \
                        int ks = kh * 2 + k2;                                  \
                        mma_f16(agg[nt], ahh + 4*ks, bp[2*k2], bp[2*k2+1]);    \
                    }                                                          \
                }                                                              \
            }                                                                  \
        }

        // stage 0: mma1 e0,e1 -> P0, P1
        DO_MMA1(Wt[0], Pt01[0])
        DO_MMA1(Wt[1], Pt01[1])
        __syncthreads();                        // sync 2: P0/P1 ready

        // stage 1: mma2 e0,e1 + mma1 e2,e3 -> P2/P3 (dead W0/W1 tiles)
        DO_MMA2(Ht[0], Pt01[0])
        DO_MMA1(Wt[2], Pt23[0])
        DO_MMA2(Ht[1], Pt01[1])
        DO_MMA1(Wt[3], Pt23[1])
        __syncthreads();                        // sync 3: P2/P3 ready

        // stage 2: mma2 e2,e3 + uniform node-lin quarter
        DO_MMA2(Ht[2], Pt23[0])
        DO_MMA2(Ht[3], Pt23[1])
        if (wc == (eg >> 1)) {
            uint32_t wB = smem_u32(NWt);
            int ntb = (eg & 1) * 2;
#pragma unroll
            for (int kh = 0; kh < 2; kh++) {
#pragma unroll
                for (int ntl = 0; ntl < 2; ntl++) {
                    uint32_t bw[4];
                    uint32_t off = (uint32_t)((kh * 32 + g * 8 + lr) * LDA + ntl * 8) * 2;
                    LDM_X4T(bw[0], bw[1], bw[2], bw[3], wB + off);
#pragma unroll
                    for (int k2 = 0; k2 < 2; k2++) {
                        int ks = kh * 2 + k2;
                        mma_f16(agg[ntb + ntl], xh + 4*ks, bw[2*k2], bw[2*k2+1]);
                    }
                }
            }
        }
#undef DO_MMA1
#undef DO_MMA2

        // ---- store partial ----
        float* Cdst = g_part[eg] + bt * (Nn * FOUTn);
#pragma unroll
        for (int nt = 0; nt < 4; nt++) {
            int col = wc * 32 + nt * 8 + cc2;
            *(float2*)(Cdst + (wr * 16 + cr) * FOUTn + col)     = make_float2(agg[nt][0], agg[nt][1]);
            *(float2*)(Cdst + (wr * 16 + cr + 8) * FOUTn + col) = make_float2(agg[nt][2], agg[nt][3]);
        }

        // ---- per-bt finisher: last of 4 eg-blocks sums + gelu + out ----
        __threadfence();
        __syncthreads();
        if (tid == 0) s_old = atomicAdd(&g_btcnt[bt], 1u);
        __syncthreads();
        if (s_old == 3u) {
            __threadfence();
            int base = bt * (Nn * FOUTn);
#pragma unroll
            for (int l = 0; l < 4; l++) {
                int idx = tid + l * 256;          // 1024 float4 tasks for this bt
                int e0 = base + idx * 4;
                int o  = (idx * 4) & 63;
                float4 p0 = *(const float4*)(g_part[0] + e0);
                float4 p1 = *(const float4*)(g_part[1] + e0);
                float4 p2 = *(const float4*)(g_part[2] + e0);
                float4 p3 = *(const float4*)(g_part[3] + e0);
                float4 nbv = *(const float4*)(nb + o);
                float4 t2v = *(const float4*)(g_T2 + bt * FOUTn + o);
                float v0 = p0.x + p1.x + p2.x + p3.x + nbv.x + t2v.x;
                float v1 = p0.y + p1.y + p2.y + p3.y + nbv.y + t2v.y;
                float v2 = p0.z + p1.z + p2.z + p3.z + nbv.z + t2v.z;
                float v3 = p0.w + p1.w + p2.w + p3.w + nbv.w + t2v.w;
                *(float4*)(out + e0) = make_float4(gelu_exact(v0), gelu_exact(v1),
                                                   gelu_exact(v2), gelu_exact(v3));
            }
            if (tid == 0) g_btcnt[bt] = 0;        // reset for next graph replay
        }
    }
}

extern "C" void kernel_launch(void* const* d_in, const int* in_sizes, int n_in,
                              void* d_out, int out_size) {
    const float* x   = (const float*)d_in[0];
    const float* adj = (const float*)d_in[1];
    const float* ew1 = (const float*)d_in[2];
    const float* eb1 = (const float*)d_in[3];
    const float* ew2 = (const float*)d_in[4];
    const float* eb2 = (const float*)d_in[5];
    const float* nw  = (const float*)d_in[6];
    const float* nb  = (const float*)d_in[7];
    const float* gw  = (const float*)d_in[8];
    const float* gb  = (const float*)d_in[9];
    const float* gms = (const float*)d_in[10];
    float* out = (float*)d_out;

    cudaFuncSetAttribute(k_all, cudaFuncAttributeMaxDynamicSharedMemorySize, FUS_SMEM);
    k_all<<<NBLK, 256, FUS_SMEM>>>(x, adj, ew1, eb1, ew2, eb2, nw, nb, gw, gb, gms, out);
}